// round 1
// baseline (speedup 1.0000x reference)
#include <cuda_runtime.h>
#include <math.h>

// Problem dims (fixed by the reference)
#define BQ 8
#define SQ 2048
#define DQ 512
#define IQ 2048
#define MQ (BQ * SQ)            // 16384 rows of x
#define BI (BQ * IQ)            // 16384 scan lanes

// GEMM tiling
#define BM 128
#define BN 64
#define BK 16
#define TM 8
#define TN 4

// Scratch for adaptive_alpha (A) and drive (C), layout [S, B*I] so the scan
// kernel reads one fully-coalesced 64KB slab per timestep.
__device__ float g_A[(size_t)MQ * IQ];
__device__ float g_C[(size_t)MQ * IQ];

__device__ __forceinline__ float sigmoidf_fast(float v) {
    return 1.0f / (1.0f + __expf(-v));
}

// Fused dual-projection GEMM + gate epilogue.
// pa = x @ Wa^T + ba ; pi = x @ Wi^T + bi
// a  = sigmoid(gate) * 3^{-sigmoid(pa)}
// c  = sqrt(1 - a^2) * sigmoid(pi) * pi
__global__ __launch_bounds__(256, 1)
void gemm_gate_kernel(const float* __restrict__ x,
                      const float* __restrict__ Wa,
                      const float* __restrict__ ba,
                      const float* __restrict__ Wi,
                      const float* __restrict__ bi,
                      const float* __restrict__ gate)
{
    __shared__ float xs [BK][BM];   // x tile, k-major (transposed on store)
    __shared__ float was[BK][BN];   // Wa tile, k-major
    __shared__ float wis[BK][BN];   // Wi tile, k-major

    const int tid = threadIdx.x;        // 0..255
    const int tx  = tid & 15;           // 16 thread-cols  -> TN*16 = 64 = BN
    const int ty  = tid >> 4;           // 16 thread-rows  -> TM*16 = 128 = BM
    const int m0  = blockIdx.y * BM;
    const int n0  = blockIdx.x * BN;

    float acc_a[TM][TN];
    float acc_i[TM][TN];
#pragma unroll
    for (int i = 0; i < TM; i++)
#pragma unroll
        for (int j = 0; j < TN; j++) { acc_a[i][j] = 0.f; acc_i[i][j] = 0.f; }

    for (int kt = 0; kt < DQ; kt += BK) {
        // ---- load x tile: 128 rows x 16 k = 512 float4, 2 per thread ----
#pragma unroll
        for (int j = 0; j < 2; j++) {
            int l   = tid + j * 256;
            int row = l >> 2;           // 0..127
            int kg  = l & 3;            // which float4 in the row's 16 k
            float4 v = *(const float4*)(x + (size_t)(m0 + row) * DQ + kt + kg * 4);
            xs[kg * 4 + 0][row] = v.x;
            xs[kg * 4 + 1][row] = v.y;
            xs[kg * 4 + 2][row] = v.z;
            xs[kg * 4 + 3][row] = v.w;
        }
        // ---- load Wa / Wi tiles: 64 rows x 16 k = 256 float4 each, 1 per thread ----
        {
            int row = tid >> 2;         // 0..63
            int kg  = tid & 3;
            float4 va = *(const float4*)(Wa + (size_t)(n0 + row) * DQ + kt + kg * 4);
            was[kg * 4 + 0][row] = va.x;
            was[kg * 4 + 1][row] = va.y;
            was[kg * 4 + 2][row] = va.z;
            was[kg * 4 + 3][row] = va.w;
            float4 vi = *(const float4*)(Wi + (size_t)(n0 + row) * DQ + kt + kg * 4);
            wis[kg * 4 + 0][row] = vi.x;
            wis[kg * 4 + 1][row] = vi.y;
            wis[kg * 4 + 2][row] = vi.z;
            wis[kg * 4 + 3][row] = vi.w;
        }
        __syncthreads();

#pragma unroll
        for (int kk = 0; kk < BK; kk++) {
            float af[TM], wfa[TN], wfi[TN];
            *(float4*)&af[0]  = *(const float4*)&xs[kk][ty * TM];
            *(float4*)&af[4]  = *(const float4*)&xs[kk][ty * TM + 4];
            *(float4*)&wfa[0] = *(const float4*)&was[kk][tx * TN];
            *(float4*)&wfi[0] = *(const float4*)&wis[kk][tx * TN];
#pragma unroll
            for (int im = 0; im < TM; im++) {
#pragma unroll
                for (int jn = 0; jn < TN; jn++) {
                    acc_a[im][jn] = fmaf(af[im], wfa[jn], acc_a[im][jn]);
                    acc_i[im][jn] = fmaf(af[im], wfi[jn], acc_i[im][jn]);
                }
            }
        }
        __syncthreads();
    }

    // ---- fused gate epilogue ----
    const float LN3 = 1.0986122886681098f;
#pragma unroll
    for (int jn = 0; jn < TN; jn++) {
        const int   ich   = n0 + tx * TN + jn;
        const float bav   = ba[ich];
        const float biv   = bi[ich];
        const float alpha = sigmoidf_fast(gate[ich]);
#pragma unroll
        for (int im = 0; im < TM; im++) {
            const int m  = m0 + ty * TM + im;
            const int bb = m >> 11;         // m / SQ
            const int ss = m & (SQ - 1);    // m % SQ
            float pa = acc_a[im][jn] + bav;
            float pi = acc_i[im][jn] + biv;
            float rg = sigmoidf_fast(pa);
            float ig = sigmoidf_fast(pi);
            float aa = alpha * __expf(-rg * LN3);          // alpha / 3^rg
            float cc = sqrtf(fmaxf(1.0f - aa * aa, 0.0f)) * ig * pi;
            size_t idx = ((size_t)ss * BQ + bb) * (size_t)IQ + ich;
            g_A[idx] = aa;
            g_C[idx] = cc;
        }
    }
}

// Sequential scan over S: h[t] = a[t]*h[t-1] + c[t].
// One thread per (b, i) lane; A/C are [S, B*I] so every timestep is a
// fully-coalesced load; output write is coalesced along i.
__global__ __launch_bounds__(128, 8)
void scan_kernel(float* __restrict__ out)
{
    const int tid = blockIdx.x * blockDim.x + threadIdx.x;  // 0..BI-1
    const int b = tid >> 11;            // tid / IQ
    const int i = tid & (IQ - 1);       // tid % IQ
    const float* a = g_A + tid;
    const float* c = g_C + tid;
    float* o = out + (size_t)b * SQ * IQ + i;
    float h = 0.0f;
#pragma unroll 8
    for (int t = 0; t < SQ; t++) {
        float av = a[(size_t)t * BI];
        float cv = c[(size_t)t * BI];
        h = fmaf(av, h, cv);
        o[(size_t)t * IQ] = h;
    }
}

extern "C" void kernel_launch(void* const* d_in, const int* in_sizes, int n_in,
                              void* d_out, int out_size)
{
    const float* x    = (const float*)d_in[0];
    const float* Wa   = (const float*)d_in[1];
    const float* ba   = (const float*)d_in[2];
    const float* Wi   = (const float*)d_in[3];
    const float* bi   = (const float*)d_in[4];
    const float* gate = (const float*)d_in[5];
    float* out = (float*)d_out;

    dim3 grid(IQ / BN, MQ / BM);   // (32, 128)
    gemm_gate_kernel<<<grid, 256>>>(x, Wa, ba, Wi, bi, gate);
    scan_kernel<<<BI / 128, 128>>>(out);
}

// round 2
// speedup vs baseline: 1.1314x; 1.1314x over previous
#include <cuda_runtime.h>
#include <math.h>

// Problem dims (fixed)
#define BQ 8
#define SQ 2048
#define DQ 512
#define IQ 2048
#define MQ (BQ * SQ)            // 16384
#define BI (BQ * IQ)            // 16384

// GEMM tiling
#define BM 128
#define BN 64
#define BK 16
#define XS_STRIDE 20            // conflict-free for mma fragment reads
#define WS_STRIDE 20

// Interleaved scratch: [(s*BQ+b)*IQ + i] -> (a, c) pairs
__device__ float g_AC[(size_t)MQ * IQ * 2];

__device__ __forceinline__ unsigned f2tf32(float f) {
    unsigned u;
    asm("cvt.rna.tf32.f32 %0, %1;" : "=r"(u) : "f"(f));
    return u;
}

__device__ __forceinline__ float sigmoidf_fast(float v) {
    return 1.0f / (1.0f + __expf(-v));
}

__device__ __forceinline__ void mma_tf32(float c[4], const unsigned a[4], const unsigned b[2]) {
    asm volatile(
        "mma.sync.aligned.m16n8k8.row.col.f32.tf32.tf32.f32 "
        "{%0,%1,%2,%3}, {%4,%5,%6,%7}, {%8,%9}, {%0,%1,%2,%3};\n"
        : "+f"(c[0]), "+f"(c[1]), "+f"(c[2]), "+f"(c[3])
        : "r"(a[0]), "r"(a[1]), "r"(a[2]), "r"(a[3]), "r"(b[0]), "r"(b[1]));
}

// Dual-projection tf32 tensor-core GEMM + fused gate epilogue.
__global__ __launch_bounds__(256)
void gemm_gate_kernel(const float* __restrict__ x,
                      const float* __restrict__ Wa,
                      const float* __restrict__ ba,
                      const float* __restrict__ Wi,
                      const float* __restrict__ bi,
                      const float* __restrict__ gate)
{
    __shared__ unsigned xs [BM * XS_STRIDE];   // 10240 B
    __shared__ unsigned was[BN * WS_STRIDE];   //  5120 B
    __shared__ unsigned wis[BN * WS_STRIDE];   //  5120 B

    const int tid    = threadIdx.x;
    const int wid    = tid >> 5;
    const int lane   = tid & 31;
    const int warp_m = wid & 3;       // 4 warps over M (4*32 = 128)
    const int warp_n = wid >> 2;      // 2 warps over N (2*32 = 64)
    const int r      = lane >> 2;     // 0..7
    const int cq     = lane & 3;      // 0..3
    const int m0     = blockIdx.y * BM;
    const int n0     = blockIdx.x * BN;

    float acc_a[2][4][4];
    float acc_i[2][4][4];
#pragma unroll
    for (int mt = 0; mt < 2; mt++)
#pragma unroll
        for (int nt = 0; nt < 4; nt++)
#pragma unroll
            for (int e = 0; e < 4; e++) { acc_a[mt][nt][e] = 0.f; acc_i[mt][nt][e] = 0.f; }

    for (int kt = 0; kt < DQ; kt += BK) {
        // ---- x tile: 128 rows x 16 k ----
#pragma unroll
        for (int j = 0; j < 2; j++) {
            int l   = tid + j * 256;
            int row = l >> 2;
            int kg  = l & 3;
            float4 v = *(const float4*)(x + (size_t)(m0 + row) * DQ + kt + kg * 4);
            unsigned* p = &xs[row * XS_STRIDE + kg * 4];
            p[0] = f2tf32(v.x); p[1] = f2tf32(v.y); p[2] = f2tf32(v.z); p[3] = f2tf32(v.w);
        }
        // ---- Wa / Wi tiles: 64 rows x 16 k each ----
        {
            int row = tid >> 2;
            int kg  = tid & 3;
            float4 va = *(const float4*)(Wa + (size_t)(n0 + row) * DQ + kt + kg * 4);
            unsigned* pa_ = &was[row * WS_STRIDE + kg * 4];
            pa_[0] = f2tf32(va.x); pa_[1] = f2tf32(va.y); pa_[2] = f2tf32(va.z); pa_[3] = f2tf32(va.w);
            float4 vi = *(const float4*)(Wi + (size_t)(n0 + row) * DQ + kt + kg * 4);
            unsigned* pi_ = &wis[row * WS_STRIDE + kg * 4];
            pi_[0] = f2tf32(vi.x); pi_[1] = f2tf32(vi.y); pi_[2] = f2tf32(vi.z); pi_[3] = f2tf32(vi.w);
        }
        __syncthreads();

#pragma unroll
        for (int kk = 0; kk < 2; kk++) {
            const int kb = kk * 8;
            unsigned afr[2][4];
#pragma unroll
            for (int mt = 0; mt < 2; mt++) {
                int base = warp_m * 32 + mt * 16;
                afr[mt][0] = xs[(base + r)     * XS_STRIDE + kb + cq];
                afr[mt][1] = xs[(base + r + 8) * XS_STRIDE + kb + cq];
                afr[mt][2] = xs[(base + r)     * XS_STRIDE + kb + cq + 4];
                afr[mt][3] = xs[(base + r + 8) * XS_STRIDE + kb + cq + 4];
            }
            unsigned bfa[4][2], bfi[4][2];
#pragma unroll
            for (int nt = 0; nt < 4; nt++) {
                int nb = warp_n * 32 + nt * 8 + r;
                bfa[nt][0] = was[nb * WS_STRIDE + kb + cq];
                bfa[nt][1] = was[nb * WS_STRIDE + kb + cq + 4];
                bfi[nt][0] = wis[nb * WS_STRIDE + kb + cq];
                bfi[nt][1] = wis[nb * WS_STRIDE + kb + cq + 4];
            }
#pragma unroll
            for (int mt = 0; mt < 2; mt++)
#pragma unroll
                for (int nt = 0; nt < 4; nt++) {
                    mma_tf32(acc_a[mt][nt], afr[mt], bfa[nt]);
                    mma_tf32(acc_i[mt][nt], afr[mt], bfi[nt]);
                }
        }
        __syncthreads();
    }

    // ---- fused gate epilogue ----
    const float LN3 = 1.0986122886681098f;
#pragma unroll
    for (int nt = 0; nt < 4; nt++) {
        const int ich0 = n0 + warp_n * 32 + nt * 8 + 2 * cq;
        const float ba0 = __ldg(ba + ich0),     ba1 = __ldg(ba + ich0 + 1);
        const float bi0 = __ldg(bi + ich0),     bi1 = __ldg(bi + ich0 + 1);
        const float al0 = sigmoidf_fast(__ldg(gate + ich0));
        const float al1 = sigmoidf_fast(__ldg(gate + ich0 + 1));
#pragma unroll
        for (int mt = 0; mt < 2; mt++) {
#pragma unroll
            for (int ro = 0; ro < 2; ro++) {
                const int m  = m0 + warp_m * 32 + mt * 16 + r + ro * 8;
                const int bb = m >> 11;
                const int ss = m & (SQ - 1);
                const int ci = ro * 2;
                float pa0 = acc_a[mt][nt][ci]     + ba0;
                float pa1 = acc_a[mt][nt][ci + 1] + ba1;
                float pi0 = acc_i[mt][nt][ci]     + bi0;
                float pi1 = acc_i[mt][nt][ci + 1] + bi1;
                float a0 = al0 * __expf(-sigmoidf_fast(pa0) * LN3);
                float a1 = al1 * __expf(-sigmoidf_fast(pa1) * LN3);
                float c0 = sqrtf(fmaxf(1.0f - a0 * a0, 0.0f)) * sigmoidf_fast(pi0) * pi0;
                float c1 = sqrtf(fmaxf(1.0f - a1 * a1, 0.0f)) * sigmoidf_fast(pi1) * pi1;
                float4 st = make_float4(a0, c0, a1, c1);
                size_t idx = (((size_t)ss * BQ + bb) * IQ + ich0) * 2;
                *(float4*)(g_AC + idx) = st;
            }
        }
    }
}

// Sequential scan: h[t] = a*h + c. One thread per (b,i) lane; (a,c) come in
// as one coalesced float2 per step, streaming hints to bypass L2 retention.
__global__ __launch_bounds__(128, 8)
void scan_kernel(float* __restrict__ out)
{
    const int tid = blockIdx.x * blockDim.x + threadIdx.x;  // 0..BI-1
    const int b = tid >> 11;
    const int i = tid & (IQ - 1);
    const float2* ac = ((const float2*)g_AC) + tid;
    float* o = out + (size_t)b * SQ * IQ + i;
    float h = 0.0f;
#pragma unroll 16
    for (int t = 0; t < SQ; t++) {
        float2 v = __ldcs(ac + (size_t)t * BI);
        h = fmaf(v.x, h, v.y);
        __stcs(o + (size_t)t * IQ, h);
    }
}

extern "C" void kernel_launch(void* const* d_in, const int* in_sizes, int n_in,
                              void* d_out, int out_size)
{
    const float* x    = (const float*)d_in[0];
    const float* Wa   = (const float*)d_in[1];
    const float* ba   = (const float*)d_in[2];
    const float* Wi   = (const float*)d_in[3];
    const float* bi   = (const float*)d_in[4];
    const float* gate = (const float*)d_in[5];
    float* out = (float*)d_out;

    dim3 grid(IQ / BN, MQ / BM);   // (32, 128)
    gemm_gate_kernel<<<grid, 256>>>(x, Wa, ba, Wi, bi, gate);
    scan_kernel<<<BI / 128, 128>>>(out);
}

// round 6
// speedup vs baseline: 2.2333x; 1.9739x over previous
#include <cuda_runtime.h>
#include <math.h>

// Problem dims (fixed)
#define BQ 8
#define SQ 2048
#define DQ 512
#define IQ 2048
#define MQ (BQ * SQ)            // 16384
#define BI (BQ * IQ)            // 16384

// GEMM tiling
#define BM 128
#define BN 64
#define BK 16
#define XS_STRIDE 20
#define WS_STRIDE 20

// Interleaved scratch: [(s*BQ+b)*IQ + i] -> (a, c) pairs
__device__ float g_AC[(size_t)MQ * IQ * 2];

__device__ __forceinline__ unsigned f2tf32(float f) {
    unsigned u;
    asm("cvt.rna.tf32.f32 %0, %1;" : "=r"(u) : "f"(f));
    return u;
}

__device__ __forceinline__ float sigmoidf_fast(float v) {
    return 1.0f / (1.0f + __expf(-v));
}

__device__ __forceinline__ void mma_tf32(float c[4], const unsigned a[4], const unsigned b[2]) {
    asm volatile(
        "mma.sync.aligned.m16n8k8.row.col.f32.tf32.tf32.f32 "
        "{%0,%1,%2,%3}, {%4,%5,%6,%7}, {%8,%9}, {%0,%1,%2,%3};\n"
        : "+f"(c[0]), "+f"(c[1]), "+f"(c[2]), "+f"(c[3])
        : "r"(a[0]), "r"(a[1]), "r"(a[2]), "r"(a[3]), "r"(b[0]), "r"(b[1]));
}

// Dual-projection tf32 tensor-core GEMM + fused gate epilogue.
// Register-prefetch double buffering: next tile's LDGs issue before the
// current tile's MMA phase, hiding DRAM/L2 latency under compute.
__global__ __launch_bounds__(256)
void gemm_gate_kernel(const float* __restrict__ x,
                      const float* __restrict__ Wa,
                      const float* __restrict__ ba,
                      const float* __restrict__ Wi,
                      const float* __restrict__ bi,
                      const float* __restrict__ gate)
{
    __shared__ unsigned xs [BM * XS_STRIDE];
    __shared__ unsigned was[BN * WS_STRIDE];
    __shared__ unsigned wis[BN * WS_STRIDE];

    const int tid    = threadIdx.x;
    const int wid    = tid >> 5;
    const int lane   = tid & 31;
    const int warp_m = wid & 3;
    const int warp_n = wid >> 2;
    const int r      = lane >> 2;
    const int cq     = lane & 3;
    const int m0     = blockIdx.y * BM;
    const int n0     = blockIdx.x * BN;

    // per-thread load slots
    const int xrow0 = tid >> 2;            // 0..63   (j=0)
    const int xrow1 = (tid + 256) >> 2;    // 64..127 (j=1)
    const int xkg   = tid & 3;
    const int wrow  = tid >> 2;
    const int wkg   = tid & 3;

    float acc_a[2][4][4];
    float acc_i[2][4][4];
#pragma unroll
    for (int mt = 0; mt < 2; mt++)
#pragma unroll
        for (int nt = 0; nt < 4; nt++)
#pragma unroll
            for (int e = 0; e < 4; e++) { acc_a[mt][nt][e] = 0.f; acc_i[mt][nt][e] = 0.f; }

    // prefetch tile 0
    float4 px0 = *(const float4*)(x  + (size_t)(m0 + xrow0) * DQ + xkg * 4);
    float4 px1 = *(const float4*)(x  + (size_t)(m0 + xrow1) * DQ + xkg * 4);
    float4 pwa = *(const float4*)(Wa + (size_t)(n0 + wrow)  * DQ + wkg * 4);
    float4 pwi = *(const float4*)(Wi + (size_t)(n0 + wrow)  * DQ + wkg * 4);

    for (int kt = 0; kt < DQ; kt += BK) {
        // ---- commit prefetched regs to smem (with rna tf32 rounding) ----
        {
            unsigned* p0 = &xs[xrow0 * XS_STRIDE + xkg * 4];
            p0[0] = f2tf32(px0.x); p0[1] = f2tf32(px0.y); p0[2] = f2tf32(px0.z); p0[3] = f2tf32(px0.w);
            unsigned* p1 = &xs[xrow1 * XS_STRIDE + xkg * 4];
            p1[0] = f2tf32(px1.x); p1[1] = f2tf32(px1.y); p1[2] = f2tf32(px1.z); p1[3] = f2tf32(px1.w);
            unsigned* pa_ = &was[wrow * WS_STRIDE + wkg * 4];
            pa_[0] = f2tf32(pwa.x); pa_[1] = f2tf32(pwa.y); pa_[2] = f2tf32(pwa.z); pa_[3] = f2tf32(pwa.w);
            unsigned* pi_ = &wis[wrow * WS_STRIDE + wkg * 4];
            pi_[0] = f2tf32(pwi.x); pi_[1] = f2tf32(pwi.y); pi_[2] = f2tf32(pwi.z); pi_[3] = f2tf32(pwi.w);
        }
        __syncthreads();

        // ---- issue next tile's global loads (latency hidden by MMA phase) ----
        const int ktn = kt + BK;
        if (ktn < DQ) {
            px0 = *(const float4*)(x  + (size_t)(m0 + xrow0) * DQ + ktn + xkg * 4);
            px1 = *(const float4*)(x  + (size_t)(m0 + xrow1) * DQ + ktn + xkg * 4);
            pwa = *(const float4*)(Wa + (size_t)(n0 + wrow)  * DQ + ktn + wkg * 4);
            pwi = *(const float4*)(Wi + (size_t)(n0 + wrow)  * DQ + ktn + wkg * 4);
        }

        // ---- MMA phase ----
#pragma unroll
        for (int kk = 0; kk < 2; kk++) {
            const int kb = kk * 8;
            unsigned afr[2][4];
#pragma unroll
            for (int mt = 0; mt < 2; mt++) {
                int base = warp_m * 32 + mt * 16;
                afr[mt][0] = xs[(base + r)     * XS_STRIDE + kb + cq];
                afr[mt][1] = xs[(base + r + 8) * XS_STRIDE + kb + cq];
                afr[mt][2] = xs[(base + r)     * XS_STRIDE + kb + cq + 4];
                afr[mt][3] = xs[(base + r + 8) * XS_STRIDE + kb + cq + 4];
            }
            unsigned bfa[4][2], bfi[4][2];
#pragma unroll
            for (int nt = 0; nt < 4; nt++) {
                int nb = warp_n * 32 + nt * 8 + r;
                bfa[nt][0] = was[nb * WS_STRIDE + kb + cq];
                bfa[nt][1] = was[nb * WS_STRIDE + kb + cq + 4];
                bfi[nt][0] = wis[nb * WS_STRIDE + kb + cq];
                bfi[nt][1] = wis[nb * WS_STRIDE + kb + cq + 4];
            }
#pragma unroll
            for (int mt = 0; mt < 2; mt++)
#pragma unroll
                for (int nt = 0; nt < 4; nt++) {
                    mma_tf32(acc_a[mt][nt], afr[mt], bfa[nt]);
                    mma_tf32(acc_i[mt][nt], afr[mt], bfi[nt]);
                }
        }
        __syncthreads();
    }

    // ---- fused gate epilogue ----
    const float LN3 = 1.0986122886681098f;
#pragma unroll
    for (int nt = 0; nt < 4; nt++) {
        const int ich0 = n0 + warp_n * 32 + nt * 8 + 2 * cq;
        const float ba0 = __ldg(ba + ich0),     ba1 = __ldg(ba + ich0 + 1);
        const float bi0 = __ldg(bi + ich0),     bi1 = __ldg(bi + ich0 + 1);
        const float al0 = sigmoidf_fast(__ldg(gate + ich0));
        const float al1 = sigmoidf_fast(__ldg(gate + ich0 + 1));
#pragma unroll
        for (int mt = 0; mt < 2; mt++) {
#pragma unroll
            for (int ro = 0; ro < 2; ro++) {
                const int m  = m0 + warp_m * 32 + mt * 16 + r + ro * 8;
                const int bb = m >> 11;
                const int ss = m & (SQ - 1);
                const int ci = ro * 2;
                float pa0 = acc_a[mt][nt][ci]     + ba0;
                float pa1 = acc_a[mt][nt][ci + 1] + ba1;
                float pi0 = acc_i[mt][nt][ci]     + bi0;
                float pi1 = acc_i[mt][nt][ci + 1] + bi1;
                float a0 = al0 * __expf(-sigmoidf_fast(pa0) * LN3);
                float a1 = al1 * __expf(-sigmoidf_fast(pa1) * LN3);
                float c0 = sqrtf(fmaxf(1.0f - a0 * a0, 0.0f)) * sigmoidf_fast(pi0) * pi0;
                float c1 = sqrtf(fmaxf(1.0f - a1 * a1, 0.0f)) * sigmoidf_fast(pi1) * pi1;
                float4 st = make_float4(a0, c0, a1, c1);
                size_t idx = (((size_t)ss * BQ + bb) * IQ + ich0) * 2;
                *(float4*)(g_AC + idx) = st;
            }
        }
    }
}

// Sequential scan: h[t] = a*h + c. Double-buffered batches of U steps keep
// ~16 loads in flight per thread; plain loads (no .cs hints).
#define SCAN_U 8
__global__ __launch_bounds__(128)
void scan_kernel(float* __restrict__ out)
{
    const int tid = blockIdx.x * blockDim.x + threadIdx.x;  // 0..BI-1
    const int b = tid >> 11;
    const int i = tid & (IQ - 1);
    const float2* ac = ((const float2*)g_AC) + tid;
    float* o = out + (size_t)b * SQ * IQ + i;

    float2 buf[SCAN_U];
#pragma unroll
    for (int u = 0; u < SCAN_U; u++) buf[u] = ac[(size_t)u * BI];

    float h = 0.0f;
    for (int t0 = 0; t0 < SQ; t0 += SCAN_U) {
        float2 nxt[SCAN_U];
        const int tn = t0 + SCAN_U;
        if (tn < SQ) {
#pragma unroll
            for (int u = 0; u < SCAN_U; u++) nxt[u] = ac[(size_t)(tn + u) * BI];
        }
#pragma unroll
        for (int u = 0; u < SCAN_U; u++) {
            h = fmaf(buf[u].x, h, buf[u].y);
            o[(size_t)(t0 + u) * IQ] = h;
        }
#pragma unroll
        for (int u = 0; u < SCAN_U; u++) buf[u] = nxt[u];
    }
}

extern "C" void kernel_launch(void* const* d_in, const int* in_sizes, int n_in,
                              void* d_out, int out_size)
{
    const float* x    = (const float*)d_in[0];
    const float* Wa   = (const float*)d_in[1];
    const float* ba   = (const float*)d_in[2];
    const float* Wi   = (const float*)d_in[3];
    const float* bi   = (const float*)d_in[4];
    const float* gate = (const float*)d_in[5];
    float* out = (float*)d_out;

    dim3 grid(IQ / BN, MQ / BM);   // (32, 128)
    gemm_gate_kernel<<<grid, 256>>>(x, Wa, ba, Wi, bi, gate);
    scan_kernel<<<BI / 128, 128>>>(out);
}